// round 13
// baseline (speedup 1.0000x reference)
#include <cuda_runtime.h>
#include <math.h>

// ---------------- problem constants ----------------
#define Nn    101376          // total nodes
#define Ee    202752          // total edges
#define Gg    528             // graphs
#define NPGc  192             // nodes per graph
#define KTOP  30              // sort-pool k
#define Dd    769             // concat channel dim
#define MAXDEG 32

// ---------------- scratch layout in one zero-init device global -------------
static const size_t OF_H   = 0;                                  // [N,256] gemm temp
static const size_t OF_X1  = OF_H   + (size_t)Nn*256;
static const size_t OF_X2  = OF_X1  + (size_t)Nn*256;
static const size_t OF_X3  = OF_X2  + (size_t)Nn*256;
static const size_t OF_X4  = OF_X3  + (size_t)Nn*256;            // [N]
static const size_t OF_H4  = OF_X4  + (size_t)Nn;                // [N]
static const size_t OF_DIS = OF_H4  + (size_t)Nn;                // [N]
static const size_t OF_XS  = OF_DIS + (size_t)Nn;                // [G*K, 769]
static const size_t OF_Y5  = OF_XS  + (size_t)Gg*KTOP*Dd;        // [G*30, 128]
static const size_t OF_Y2  = OF_Y5  + (size_t)Gg*30*128;         // [G,15,128]
static const size_t OF_W5T = OF_Y2  + (size_t)Gg*15*128;         // [769,128]
static const size_t OF_W6T = OF_W5T + (size_t)769*128;           // [640,256]
static const size_t OF_O6  = OF_W6T + (size_t)640*256;           // [48,30976]
static const size_t OF_EMT = OF_O6  + (size_t)48*30976;          // [30976,48]
static const size_t OF_HP  = OF_EMT + (size_t)48*30976;          // [48,256]
static const size_t OF_END = OF_HP  + (size_t)48*256;
__device__ float g_f[OF_END];

static const size_t OI_CNT = 0;                                  // [N]
static const size_t OI_ADJ = OI_CNT + (size_t)Nn;                // [N,32]
static const size_t OI_IDX = OI_ADJ + (size_t)Nn*MAXDEG;         // [G,30]
static const size_t OI_AOF = OI_IDX + (size_t)Gg*KTOP;           // [5808]
static const size_t OI_COF = OI_AOF + 5808;                      // [5808]
static const size_t OI_END = OI_COF + 5808;
__device__ int g_i[OI_END];

// ---------------- f32x2 packed helpers ----------------
typedef unsigned long long u64;
__device__ __forceinline__ u64 ffma2(u64 a, u64 b, u64 c) {
    u64 d;
    asm("fma.rn.f32x2 %0, %1, %2, %3;" : "=l"(d) : "l"(a), "l"(b), "l"(c));
    return d;
}
__device__ __forceinline__ u64 pack2(float lo, float hi) {
    u64 d;
    asm("mov.b64 %0, {%1, %2};" : "=l"(d) : "f"(lo), "f"(hi));
    return d;
}
__device__ __forceinline__ void unpack2(u64 v, float& lo, float& hi) {
    asm("mov.b64 {%0, %1}, %2;" : "=f"(lo), "=f"(hi) : "l"(v));
}

// ---------------- small utility kernels ----------------
__global__ void k_zero_cnt() {
    int i = blockIdx.x*blockDim.x + threadIdx.x;
    if (i < Nn) g_i[OI_CNT + i] = 0;
}
__global__ void k_zero_hp() {
    int i = blockIdx.x*blockDim.x + threadIdx.x;
    if (i < 48*256) g_f[OF_HP + i] = 0.f;
}

// build fixed-width adjacency (incoming edges per dst)
__global__ void k_build(const int* __restrict__ src, const int* __restrict__ dst) {
    int e = blockIdx.x*blockDim.x + threadIdx.x;
    if (e >= Ee) return;
    int d = dst[e];
    int p = atomicAdd(&g_i[OI_CNT + d], 1);
    if (p < MAXDEG) g_i[OI_ADJ + (size_t)d*MAXDEG + p] = src[e];
}

// deterministic order (sort adjacency) + dis = rsqrt(deg)
__global__ void k_dis() {
    int i = blockIdx.x*blockDim.x + threadIdx.x;
    if (i >= Nn) return;
    int n = g_i[OI_CNT + i]; if (n > MAXDEG) n = MAXDEG;
    g_i[OI_CNT + i] = n;
    int* a = &g_i[OI_ADJ + (size_t)i*MAXDEG];
    for (int p = 1; p < n; p++) {
        int key = a[p]; int q = p-1;
        while (q >= 0 && a[q] > key) { a[q+1] = a[q]; q--; }
        a[q+1] = key;
    }
    g_f[OF_DIS + i] = rsqrtf(1.0f + (float)n);
}

// ---------------- multi-tile double-buffered f32x2 SGEMM --------------------
// C[M,N] = A[M,K] * B[K,N]. 128x128 tile, 256 threads, thread tile 16x4.
// Each block processes `mtiles` row-tiles at stride gridDim.y*128, as one
// continuous double-buffered k-tile stream (prologue paid once per block).
// __launch_bounds__(256,2) caps regs at 128 -> 2 blocks/SM (4 warps/SMSP).
#define PREF_TILE(k0, bmv) do {                                                \
    if (vecA) {                                                                \
        _Pragma("unroll") for (int l = 0; l < 2; l++) {                        \
            int idx = l*256 + tid, r = idx >> 2, c4 = idx & 3;                 \
            int row = (bmv) + r;                                               \
            pa[l] = make_float4(0.f,0.f,0.f,0.f);                              \
            if (row < M) {                                                     \
                long base = useAOF ? (long)g_i[OI_AOF+row] : (long)row*lda;    \
                pa[l] = *(const float4*)&A[base + (k0) + c4*4];                \
            }                                                                  \
        }                                                                      \
    } else {                                                                   \
        _Pragma("unroll") for (int l = 0; l < 8; l++) {                        \
            int lin = l*256 + tid, r = lin >> 4, c = lin & 15;                 \
            int row = (bmv) + r;                                               \
            pas[l] = 0.f;                                                      \
            if (row < M && (k0) + c < K) {                                     \
                long base = useAOF ? (long)g_i[OI_AOF+row] : (long)row*lda;    \
                pas[l] = A[base + (k0) + c];                                   \
            }                                                                  \
        }                                                                      \
    }                                                                          \
    _Pragma("unroll") for (int l = 0; l < 2; l++) {                            \
        int idx = l*256 + tid, kr = idx >> 5, cc = idx & 31;                   \
        pb[l] = make_float4(0.f,0.f,0.f,0.f);                                  \
        if ((k0) + kr < K) pb[l] = *(const float4*)&B[(long)((k0)+kr)*N + bn + cc*4]; \
    }                                                                          \
} while(0)

#define STORE_TILE(bsel) do {                                                  \
    if (vecA) {                                                                \
        _Pragma("unroll") for (int l = 0; l < 2; l++) {                        \
            int idx = l*256 + tid, r = idx >> 2, c4 = idx & 3;                 \
            As[bsel][(c4*4+0)*132 + r] = pa[l].x;                              \
            As[bsel][(c4*4+1)*132 + r] = pa[l].y;                              \
            As[bsel][(c4*4+2)*132 + r] = pa[l].z;                              \
            As[bsel][(c4*4+3)*132 + r] = pa[l].w;                              \
        }                                                                      \
    } else {                                                                   \
        _Pragma("unroll") for (int l = 0; l < 8; l++) {                        \
            int lin = l*256 + tid, r = lin >> 4, c = lin & 15;                 \
            As[bsel][c*132 + r] = pas[l];                                      \
        }                                                                      \
    }                                                                          \
    _Pragma("unroll") for (int l = 0; l < 2; l++) {                            \
        int idx = l*256 + tid, kr = idx >> 5, cc = idx & 31;                   \
        *(float4*)&Bs[bsel][kr*132 + cc*4] = pb[l];                            \
    }                                                                          \
} while(0)

__global__ __launch_bounds__(256, 2)
void sgemm2(const float* __restrict__ Aext, size_t Aoff, int lda, int useAOF, int vecA,
            const float* __restrict__ Bext, size_t Boff,
            size_t Coff, int useCOF, int cstride,
            int M, int N, int K,
            const float* __restrict__ bias, int act, int mtiles) {
    const float* A = Aext ? Aext : (const float*)(g_f + Aoff);
    const float* B = Bext ? Bext : (const float*)(g_f + Boff);
    float* C = g_f + Coff;

    __shared__ __align__(16) float As[2][16*132];
    __shared__ __align__(16) float Bs[2][16*132];
    const int tid = threadIdx.x;
    const int bn = blockIdx.x * 128;
    const int bmStep = gridDim.y * 128;
    const int ty = tid >> 5;          // 0..7  -> rows ty*16..+15
    const int tx = tid & 31;          // 0..31 -> cols tx*4..+3

    u64 acc[8][4];
    #pragma unroll
    for (int i = 0; i < 8; i++)
        #pragma unroll
        for (int j = 0; j < 4; j++) acc[i][j] = 0ull;

    const int T = (K + 15) >> 4;
    const int S = T * mtiles;
    float4 pa[2]; float pas[8]; float4 pb[2];

    int bmCur = blockIdx.y * 128;
    PREF_TILE(0, bmCur);
    STORE_TILE(0);
    __syncthreads();

    for (int s = 0; s < S; s++) {
        const int cb = s & 1;
        const int mt = s / T;
        const int t  = s - mt * T;
        if (s + 1 < S) {
            int sn = s + 1;
            int mtn = sn / T;
            int tn  = sn - mtn * T;
            int bmn = blockIdx.y * 128 + mtn * bmStep;
            PREF_TILE(tn << 4, bmn);
        }

        #pragma unroll
        for (int kk = 0; kk < 16; kk++) {
            const ulonglong2* ap = (const ulonglong2*)&As[cb][kk*132 + ty*16];
            u64 a2[8];
            #pragma unroll
            for (int i = 0; i < 4; i++) {
                ulonglong2 q = ap[i];
                a2[2*i] = q.x; a2[2*i+1] = q.y;
            }
            float4 bv = *(const float4*)&Bs[cb][kk*132 + tx*4];
            u64 bd0 = pack2(bv.x, bv.x), bd1 = pack2(bv.y, bv.y);
            u64 bd2 = pack2(bv.z, bv.z), bd3 = pack2(bv.w, bv.w);
            #pragma unroll
            for (int r = 0; r < 8; r++) {
                acc[r][0] = ffma2(a2[r], bd0, acc[r][0]);
                acc[r][1] = ffma2(a2[r], bd1, acc[r][1]);
                acc[r][2] = ffma2(a2[r], bd2, acc[r][2]);
                acc[r][3] = ffma2(a2[r], bd3, acc[r][3]);
            }
        }

        if (t == T - 1) {
            // epilogue for this m-tile, then reset accumulators
            #pragma unroll
            for (int r = 0; r < 8; r++) {
                #pragma unroll
                for (int ss = 0; ss < 2; ss++) {
                    int row = bmCur + ty*16 + 2*r + ss;
                    if (row >= M) continue;
                    long cbase = useCOF ? (long)g_i[OI_COF + row] : (long)row * N;
                    float v[4];
                    #pragma unroll
                    for (int c = 0; c < 4; c++) {
                        float lo, hi; unpack2(acc[r][c], lo, hi);
                        v[c] = ss ? hi : lo;
                        if (bias) v[c] += bias[bn + tx*4 + c];
                        if (act == 1) v[c] = fmaxf(v[c], 0.f);
                    }
                    if (cstride == 1) {
                        *(float4*)&C[cbase + bn + tx*4] = make_float4(v[0],v[1],v[2],v[3]);
                    } else {
                        #pragma unroll
                        for (int c = 0; c < 4; c++)
                            C[cbase + (long)(bn + tx*4 + c) * cstride] = v[c];
                    }
                }
            }
            #pragma unroll
            for (int i = 0; i < 8; i++)
                #pragma unroll
                for (int j = 0; j < 4; j++) acc[i][j] = 0ull;
            bmCur += bmStep;
        }

        if (s + 1 < S) {
            STORE_TILE(1 - cb);
            __syncthreads();
        }
    }
}

// ---------------- GCN aggregation (C=256, float4): 4 nodes per block --------
__global__ void k_agg(size_t outOff, const float* __restrict__ bias) {
    const float4* h = (const float4*)(g_f + OF_H);
    int node = blockIdx.x*4 + (threadIdx.x >> 6);
    int c4 = threadIdx.x & 63;
    float di = g_f[OF_DIS + node];
    float4 hv = h[(size_t)node*64 + c4];
    float w0 = di * di;
    float4 v = make_float4(hv.x*w0, hv.y*w0, hv.z*w0, hv.w*w0);
    int n = g_i[OI_CNT + node];
    const int* a = &g_i[OI_ADJ + (size_t)node*MAXDEG];
    for (int e = 0; e < n; e++) {
        int s = a[e];
        float w = g_f[OF_DIS + s] * di;
        float4 hn = h[(size_t)s*64 + c4];
        v.x += hn.x*w; v.y += hn.y*w; v.z += hn.z*w; v.w += hn.w*w;
    }
    float4 b = ((const float4*)bias)[c4];
    float4 o = make_float4(tanhf(v.x + b.x), tanhf(v.y + b.y),
                           tanhf(v.z + b.z), tanhf(v.w + b.w));
    ((float4*)(g_f + outOff))[(size_t)node*64 + c4] = o;
}

// layer-4 projection: h4[n] = dot(x3[n,:256], W4)  (warp per node)
__global__ void k_l4(const float* __restrict__ W4) {
    int warp = (blockIdx.x*blockDim.x + threadIdx.x) >> 5;
    int lane = threadIdx.x & 31;
    if (warp >= Nn) return;
    const float* row = g_f + OF_X3 + (size_t)warp*256;
    float s = 0.f;
    #pragma unroll
    for (int c = lane; c < 256; c += 32) s += row[c] * W4[c];
    #pragma unroll
    for (int o = 16; o; o >>= 1) s += __shfl_xor_sync(0xffffffffu, s, o);
    if (lane == 0) g_f[OF_H4 + warp] = s;
}

// aggregation C=1 + tanh -> x4
__global__ void k_agg1(const float* __restrict__ b4) {
    int i = blockIdx.x*blockDim.x + threadIdx.x;
    if (i >= Nn) return;
    const float* h = g_f + OF_H4;
    float di = g_f[OF_DIS + i];
    float v = h[i] * di * di;
    int n = g_i[OI_CNT + i];
    const int* a = &g_i[OI_ADJ + (size_t)i*MAXDEG];
    for (int e = 0; e < n; e++) { int s = a[e]; v += h[s] * g_f[OF_DIS + s] * di; }
    g_f[OF_X4 + i] = tanhf(v + b4[0]);
}

// per-graph top-K by last channel: bitonic sort of 256 (value desc, idx asc)
__global__ void k_topk() {
    __shared__ float key[256];
    __shared__ int   val[256];
    int g = blockIdx.x, t = threadIdx.x;
    key[t] = (t < NPGc) ? g_f[OF_X4 + (size_t)g*NPGc + t] : -2.0f;  // tanh in (-1,1)
    val[t] = t;
    __syncthreads();
    for (int k = 2; k <= 256; k <<= 1) {
        for (int j = k >> 1; j > 0; j >>= 1) {
            int ixj = t ^ j;
            if (ixj > t) {
                float ka = key[t], kb = key[ixj];
                int   va = val[t], vb = val[ixj];
                bool before = (ka > kb) || (ka == kb && va < vb);
                bool dir = ((t & k) == 0);
                if (before != dir) { key[t]=kb; key[ixj]=ka; val[t]=vb; val[ixj]=va; }
            }
            __syncthreads();
        }
    }
    if (t < KTOP) g_i[OI_IDX + g*KTOP + t] = val[t];
}

// gather selected rows into xs [G*K, 769]
__global__ void k_gather() {
    int m = blockIdx.x;                 // 0..15839
    int g = m / KTOP;
    int node = g*NPGc + g_i[OI_IDX + m];
    int c = threadIdx.x;
    float* row = g_f + OF_XS + (size_t)m * Dd;
    row[c]       = g_f[OF_X1 + (size_t)node*256 + c];
    row[256 + c] = g_f[OF_X2 + (size_t)node*256 + c];
    row[512 + c] = g_f[OF_X3 + (size_t)node*256 + c];
    if (c == 0) row[768] = g_f[OF_X4 + node];
}

// weight re-layouts
__global__ void k_w5t(const float* __restrict__ w5) {
    int i = blockIdx.x*blockDim.x + threadIdx.x;
    if (i >= 769*128) return;
    int d = i >> 7, oc = i & 127;
    g_f[OF_W5T + i] = w5[oc*Dd + d];
}
__global__ void k_w6t(const float* __restrict__ w6) {
    int i = blockIdx.x*blockDim.x + threadIdx.x;
    if (i >= 640*256) return;
    int k = i >> 8, o = i & 255;
    int ic = k & 127, j = k >> 7;
    g_f[OF_W6T + i] = w6[o*640 + ic*5 + j];
}
__global__ void k_off6() {
    int m = blockIdx.x*blockDim.x + threadIdx.x;
    if (m >= 5808) return;
    int g = m / 11, t = m - g*11;
    g_i[OI_AOF + m] = g*15*128 + t*128;   // A row start inside y2 buffer
    g_i[OI_COF + m] = g*2816 + t;         // out6 base; +oc2*11
}

// maxpool(2,2) over conv5 output -> y2 [G,15,128]
__global__ void k_pool() {
    int i = blockIdx.x*blockDim.x + threadIdx.x;
    if (i >= Gg*15*128) return;
    int oc = i & 127;
    int r = i >> 7;
    int p = r % 15, g = r / 15;
    float a = g_f[OF_Y5 + (size_t)(g*30 + 2*p)*128 + oc];
    float b = g_f[OF_Y5 + (size_t)(g*30 + 2*p + 1)*128 + oc];
    g_f[OF_Y2 + i] = fmaxf(a, b);
}

// transpose emb (=out6) [48,30976] -> embT [30976,48]
__global__ void k_embT() {
    int k = blockIdx.x*blockDim.x + threadIdx.x;
    if (k >= 30976) return;
    #pragma unroll 4
    for (int b = 0; b < 48; b++)
        g_f[OF_EMT + (size_t)k*48 + b] = g_f[OF_O6 + (size_t)b*30976 + k];
}

// dense1: hpre[b,o] += sum_k emb[b,k]*Wc1[k,o]  (split-K, atomic reduce)
__global__ __launch_bounds__(256)
void k_dense1(const float* __restrict__ Wc1) {
    const int KC = 242;                 // 128 blocks * 242 = 30976
    int o = threadIdx.x;
    int k0 = blockIdx.x * KC;
    float acc[48];
    #pragma unroll
    for (int b = 0; b < 48; b++) acc[b] = 0.f;
    __shared__ __align__(16) float esm[22*48];
    for (int s = 0; s < KC; s += 22) {
        for (int l = threadIdx.x; l < 22*48; l += 256)
            esm[l] = g_f[OF_EMT + (size_t)(k0+s)*48 + l];
        __syncthreads();
        #pragma unroll 2
        for (int kk = 0; kk < 22; kk++) {
            float w = Wc1[(size_t)(k0+s+kk)*256 + o];
            const float4* e4 = (const float4*)&esm[kk*48];
            #pragma unroll
            for (int bb = 0; bb < 12; bb++) {
                float4 e = e4[bb];
                acc[bb*4+0] += e.x*w; acc[bb*4+1] += e.y*w;
                acc[bb*4+2] += e.z*w; acc[bb*4+3] += e.w*w;
            }
        }
        __syncthreads();
    }
    #pragma unroll
    for (int b = 0; b < 48; b++) atomicAdd(&g_f[OF_HP + b*256 + o], acc[b]);
}

// dense2: relu(hpre+bc1) @ Wc2 + bc2 -> logits [48,10]
__global__ void k_dense2(const float* __restrict__ bc1, const float* __restrict__ Wc2,
                         const float* __restrict__ bc2, float* __restrict__ out) {
    __shared__ float hs[48*256];
    int tid = threadIdx.x;
    for (int l = tid; l < 48*256; l += blockDim.x)
        hs[l] = fmaxf(g_f[OF_HP + l] + bc1[l & 255], 0.f);
    __syncthreads();
    if (tid < 480) {
        int b = tid / 10, o = tid - b*10;
        float s = bc2[o];
        for (int j = 0; j < 256; j++) s += hs[b*256 + j] * Wc2[j*10 + o];
        out[tid] = s;
    }
}

// ---------------- launch (kernel launches ONLY — no other CUDA APIs) --------
extern "C" void kernel_launch(void* const* d_in, const int* in_sizes, int n_in,
                              void* d_out, int out_size) {
    const float* x    = (const float*)d_in[0];
    const int*   src  = (const int*)  d_in[1];
    const int*   dstp = (const int*)  d_in[2];
    const float* W1   = (const float*)d_in[3];
    const float* b1   = (const float*)d_in[4];
    const float* W2   = (const float*)d_in[5];
    const float* b2   = (const float*)d_in[6];
    const float* W3   = (const float*)d_in[7];
    const float* b3   = (const float*)d_in[8];
    const float* W4   = (const float*)d_in[9];
    const float* b4   = (const float*)d_in[10];
    const float* w5   = (const float*)d_in[11];
    const float* bc5  = (const float*)d_in[12];
    const float* w6   = (const float*)d_in[13];
    const float* bc6  = (const float*)d_in[14];
    const float* Wc1  = (const float*)d_in[15];
    const float* bc1  = (const float*)d_in[16];
    const float* Wc2  = (const float*)d_in[17];
    const float* bc2  = (const float*)d_in[18];
    float* out = (float*)d_out;

    // graph structure
    k_zero_cnt<<<(Nn+255)/256, 256>>>();
    k_build<<<(Ee+255)/256, 256>>>(src, dstp);
    k_dis<<<(Nn+255)/256, 256>>>();

    // GCN layers: XW (into H) then normalize+aggregate+tanh
    // layer 1 (K=64, T=4): many small blocks (measured-best config at <=128 regs)
    sgemm2<<<dim3(2,792), 256>>>(x, 0, 64, 0, 1,  W1, 0, OF_H, 0, 1, Nn, 256, 64,  nullptr, 0, 1);
    k_agg<<<Nn/4, 256>>>(OF_X1, b1);
    // layers 2/3 (K=256, T=16): one-wave multi-tile streams
    sgemm2<<<dim3(2,132), 256>>>(nullptr, OF_X1, 256, 0, 1, W2, 0, OF_H, 0, 1, Nn, 256, 256, nullptr, 0, 6);
    k_agg<<<Nn/4, 256>>>(OF_X2, b2);
    sgemm2<<<dim3(2,132), 256>>>(nullptr, OF_X2, 256, 0, 1, W3, 0, OF_H, 0, 1, Nn, 256, 256, nullptr, 0, 6);
    k_agg<<<Nn/4, 256>>>(OF_X3, b3);
    k_l4<<<(Nn*32+255)/256, 256>>>(W4);
    k_agg1<<<(Nn+255)/256, 256>>>(b4);

    // sort-pool + gather
    k_topk<<<Gg, 256>>>();
    k_gather<<<Gg*KTOP, 256>>>();

    // weight re-layouts + offset tables (needed only before conv5/conv6)
    k_w5t<<<(769*128+255)/256, 256>>>(w5);
    k_w6t<<<(640*256+255)/256, 256>>>(w6);
    k_off6<<<(5808+255)/256, 256>>>();

    // conv5 (stride=kernel=769) as GEMM [15840,769]x[769,128] + bias + relu
    sgemm2<<<dim3(1,124), 256>>>(nullptr, OF_XS, Dd, 0, 0, nullptr, OF_W5T, OF_Y5, 0, 1,
                                 Gg*KTOP, 128, Dd, bc5, 1, 1);
    k_pool<<<(Gg*15*128+255)/256, 256>>>();

    // conv6 as GEMM with row-offset indirection [5808,640]x[640,256], permuted store
    sgemm2<<<dim3(2,46), 256>>>(nullptr, OF_Y2, 0, 1, 1, nullptr, OF_W6T, OF_O6, 1, 11,
                                5808, 256, 640, bc6, 1, 1);

    // dense head
    k_embT<<<(30976+255)/256, 256>>>();
    k_zero_hp<<<(48*256+255)/256, 256>>>();
    k_dense1<<<128, 256>>>(Wc1);
    k_dense2<<<1, 512>>>(bc1, Wc2, bc2, out);
}

// round 17
// speedup vs baseline: 1.1233x; 1.1233x over previous
#include <cuda_runtime.h>
#include <math.h>

// ---------------- problem constants ----------------
#define Nn    101376          // total nodes
#define Ee    202752          // total edges
#define Gg    528             // graphs
#define NPGc  192             // nodes per graph
#define KTOP  30              // sort-pool k
#define Dd    769             // concat channel dim
#define DdP   784             // padded row stride for conv5 (=16*49)
#define MAXDEG 32

// ---------------- scratch layout in one zero-init device global -------------
static const size_t OF_H   = 0;                                  // [N,256] gemm temp
static const size_t OF_X1  = OF_H   + (size_t)Nn*256;
static const size_t OF_X2  = OF_X1  + (size_t)Nn*256;
static const size_t OF_X3  = OF_X2  + (size_t)Nn*256;
static const size_t OF_X4  = OF_X3  + (size_t)Nn*256;            // [N]
static const size_t OF_H4  = OF_X4  + (size_t)Nn;                // [N]
static const size_t OF_DIS = OF_H4  + (size_t)Nn;                // [N]
static const size_t OF_XS  = OF_DIS + (size_t)Nn;                // [G*K, 784] (cols 769..783 stay 0)
static const size_t OF_Y5  = OF_XS  + (size_t)Gg*KTOP*DdP;       // [G*30, 128]
static const size_t OF_Y2  = OF_Y5  + (size_t)Gg*30*128;         // [G,15,128]
static const size_t OF_W5T = OF_Y2  + (size_t)Gg*15*128;         // [784,128] (rows 769..783 stay 0)
static const size_t OF_W6T = OF_W5T + (size_t)DdP*128;           // [640,256]
static const size_t OF_O6  = OF_W6T + (size_t)640*256;           // [48,30976]
static const size_t OF_EMT = OF_O6  + (size_t)48*30976;          // [30976,48]
static const size_t OF_HP  = OF_EMT + (size_t)48*30976;          // [48,256]
static const size_t OF_END = OF_HP  + (size_t)48*256;
__device__ float g_f[OF_END];

static const size_t OI_CNT = 0;                                  // [N]
static const size_t OI_ADJ = OI_CNT + (size_t)Nn;                // [N,32]
static const size_t OI_IDX = OI_ADJ + (size_t)Nn*MAXDEG;         // [G,30]
static const size_t OI_AOF = OI_IDX + (size_t)Gg*KTOP;           // [5808]
static const size_t OI_COF = OI_AOF + 5808;                      // [5808]
static const size_t OI_END = OI_COF + 5808;
__device__ int g_i[OI_END];

// ---------------- f32x2 packed helpers ----------------
typedef unsigned long long u64;
__device__ __forceinline__ u64 ffma2(u64 a, u64 b, u64 c) {
    u64 d;
    asm("fma.rn.f32x2 %0, %1, %2, %3;" : "=l"(d) : "l"(a), "l"(b), "l"(c));
    return d;
}
__device__ __forceinline__ u64 pack2(float lo, float hi) {
    u64 d;
    asm("mov.b64 %0, {%1, %2};" : "=l"(d) : "f"(lo), "f"(hi));
    return d;
}
__device__ __forceinline__ void unpack2(u64 v, float& lo, float& hi) {
    asm("mov.b64 {%0, %1}, %2;" : "=f"(lo), "=f"(hi) : "l"(v));
}

// ---------------- small utility kernels ----------------
__global__ void k_zero_cnt() {
    int i = blockIdx.x*blockDim.x + threadIdx.x;
    if (i < Nn) g_i[OI_CNT + i] = 0;
}
__global__ void k_zero_hp() {
    int i = blockIdx.x*blockDim.x + threadIdx.x;
    if (i < 48*256) g_f[OF_HP + i] = 0.f;
}

// build fixed-width adjacency (incoming edges per dst)
__global__ void k_build(const int* __restrict__ src, const int* __restrict__ dst) {
    int e = blockIdx.x*blockDim.x + threadIdx.x;
    if (e >= Ee) return;
    int d = dst[e];
    int p = atomicAdd(&g_i[OI_CNT + d], 1);
    if (p < MAXDEG) g_i[OI_ADJ + (size_t)d*MAXDEG + p] = src[e];
}

// deterministic order (sort adjacency) + dis = rsqrt(deg)
__global__ void k_dis() {
    int i = blockIdx.x*blockDim.x + threadIdx.x;
    if (i >= Nn) return;
    int n = g_i[OI_CNT + i]; if (n > MAXDEG) n = MAXDEG;
    g_i[OI_CNT + i] = n;
    int* a = &g_i[OI_ADJ + (size_t)i*MAXDEG];
    for (int p = 1; p < n; p++) {
        int key = a[p]; int q = p-1;
        while (q >= 0 && a[q] > key) { a[q+1] = a[q]; q--; }
        a[q+1] = key;
    }
    g_f[OF_DIS + i] = rsqrtf(1.0f + (float)n);
}

// ---------------- multi-tile double-buffered f32x2 SGEMM (R10 source) -------
// C[M,N] = A[M,K] * B[K,N]. 128x128 tile, 256 threads, thread tile 16x4.
// Each block processes `mtiles` row-tiles at stride gridDim.y*128, as one
// continuous double-buffered k-tile stream (prologue paid once per block).
#define PREF_TILE(k0, bmv) do {                                                \
    if (vecA) {                                                                \
        _Pragma("unroll") for (int l = 0; l < 2; l++) {                        \
            int idx = l*256 + tid, r = idx >> 2, c4 = idx & 3;                 \
            int row = (bmv) + r;                                               \
            pa[l] = make_float4(0.f,0.f,0.f,0.f);                              \
            if (row < M) {                                                     \
                long base = useAOF ? (long)g_i[OI_AOF+row] : (long)row*lda;    \
                pa[l] = *(const float4*)&A[base + (k0) + c4*4];                \
            }                                                                  \
        }                                                                      \
    } else {                                                                   \
        _Pragma("unroll") for (int l = 0; l < 8; l++) {                        \
            int lin = l*256 + tid, r = lin >> 4, c = lin & 15;                 \
            int row = (bmv) + r;                                               \
            pas[l] = 0.f;                                                      \
            if (row < M && (k0) + c < K) {                                     \
                long base = useAOF ? (long)g_i[OI_AOF+row] : (long)row*lda;    \
                pas[l] = A[base + (k0) + c];                                   \
            }                                                                  \
        }                                                                      \
    }                                                                          \
    _Pragma("unroll") for (int l = 0; l < 2; l++) {                            \
        int idx = l*256 + tid, kr = idx >> 5, cc = idx & 31;                   \
        pb[l] = make_float4(0.f,0.f,0.f,0.f);                                  \
        if ((k0) + kr < K) pb[l] = *(const float4*)&B[(long)((k0)+kr)*N + bn + cc*4]; \
    }                                                                          \
} while(0)

#define STORE_TILE(bsel) do {                                                  \
    if (vecA) {                                                                \
        _Pragma("unroll") for (int l = 0; l < 2; l++) {                        \
            int idx = l*256 + tid, r = idx >> 2, c4 = idx & 3;                 \
            As[bsel][(c4*4+0)*132 + r] = pa[l].x;                              \
            As[bsel][(c4*4+1)*132 + r] = pa[l].y;                              \
            As[bsel][(c4*4+2)*132 + r] = pa[l].z;                              \
            As[bsel][(c4*4+3)*132 + r] = pa[l].w;                              \
        }                                                                      \
    } else {                                                                   \
        _Pragma("unroll") for (int l = 0; l < 8; l++) {                        \
            int lin = l*256 + tid, r = lin >> 4, c = lin & 15;                 \
            As[bsel][c*132 + r] = pas[l];                                      \
        }                                                                      \
    }                                                                          \
    _Pragma("unroll") for (int l = 0; l < 2; l++) {                            \
        int idx = l*256 + tid, kr = idx >> 5, cc = idx & 31;                   \
        *(float4*)&Bs[bsel][kr*132 + cc*4] = pb[l];                            \
    }                                                                          \
} while(0)

__global__ __launch_bounds__(256)
void sgemm2(const float* __restrict__ Aext, size_t Aoff, int lda, int useAOF, int vecA,
            const float* __restrict__ Bext, size_t Boff,
            size_t Coff, int useCOF, int cstride,
            int M, int N, int K,
            const float* __restrict__ bias, int act, int mtiles) {
    const float* A = Aext ? Aext : (const float*)(g_f + Aoff);
    const float* B = Bext ? Bext : (const float*)(g_f + Boff);
    float* C = g_f + Coff;

    __shared__ __align__(16) float As[2][16*132];
    __shared__ __align__(16) float Bs[2][16*132];
    const int tid = threadIdx.x;
    const int bn = blockIdx.x * 128;
    const int bmStep = gridDim.y * 128;
    const int ty = tid >> 5;          // 0..7  -> rows ty*16..+15
    const int tx = tid & 31;          // 0..31 -> cols tx*4..+3

    u64 acc[8][4];
    #pragma unroll
    for (int i = 0; i < 8; i++)
        #pragma unroll
        for (int j = 0; j < 4; j++) acc[i][j] = 0ull;

    const int T = (K + 15) >> 4;
    const int S = T * mtiles;
    float4 pa[2]; float pas[8]; float4 pb[2];

    int bmCur = blockIdx.y * 128;
    PREF_TILE(0, bmCur);
    STORE_TILE(0);
    __syncthreads();

    for (int s = 0; s < S; s++) {
        const int cb = s & 1;
        const int mt = s / T;
        const int t  = s - mt * T;
        if (s + 1 < S) {
            int sn = s + 1;
            int mtn = sn / T;
            int tn  = sn - mtn * T;
            int bmn = blockIdx.y * 128 + mtn * bmStep;
            PREF_TILE(tn << 4, bmn);
        }

        #pragma unroll
        for (int kk = 0; kk < 16; kk++) {
            const ulonglong2* ap = (const ulonglong2*)&As[cb][kk*132 + ty*16];
            u64 a2[8];
            #pragma unroll
            for (int i = 0; i < 4; i++) {
                ulonglong2 q = ap[i];
                a2[2*i] = q.x; a2[2*i+1] = q.y;
            }
            float4 bv = *(const float4*)&Bs[cb][kk*132 + tx*4];
            u64 bd0 = pack2(bv.x, bv.x), bd1 = pack2(bv.y, bv.y);
            u64 bd2 = pack2(bv.z, bv.z), bd3 = pack2(bv.w, bv.w);
            #pragma unroll
            for (int r = 0; r < 8; r++) {
                acc[r][0] = ffma2(a2[r], bd0, acc[r][0]);
                acc[r][1] = ffma2(a2[r], bd1, acc[r][1]);
                acc[r][2] = ffma2(a2[r], bd2, acc[r][2]);
                acc[r][3] = ffma2(a2[r], bd3, acc[r][3]);
            }
        }

        if (t == T - 1) {
            // epilogue for this m-tile, then reset accumulators
            #pragma unroll
            for (int r = 0; r < 8; r++) {
                #pragma unroll
                for (int ss = 0; ss < 2; ss++) {
                    int row = bmCur + ty*16 + 2*r + ss;
                    if (row >= M) continue;
                    long cbase = useCOF ? (long)g_i[OI_COF + row] : (long)row * N;
                    #pragma unroll
                    for (int c = 0; c < 4; c++) {
                        int col = bn + tx*4 + c;
                        float lo, hi; unpack2(acc[r][c], lo, hi);
                        float v = ss ? hi : lo;
                        if (bias) v += bias[col];
                        if (act == 1) v = fmaxf(v, 0.f);
                        C[cbase + (long)col * cstride] = v;
                    }
                }
            }
            #pragma unroll
            for (int i = 0; i < 8; i++)
                #pragma unroll
                for (int j = 0; j < 4; j++) acc[i][j] = 0ull;
            bmCur += bmStep;
        }

        if (s + 1 < S) {
            STORE_TILE(1 - cb);
            __syncthreads();
        }
    }
}

// ---------------- GCN aggregation (C=256, float4): 4 nodes per block --------
__global__ void k_agg(size_t outOff, const float* __restrict__ bias) {
    const float4* h = (const float4*)(g_f + OF_H);
    int node = blockIdx.x*4 + (threadIdx.x >> 6);
    int c4 = threadIdx.x & 63;
    float di = g_f[OF_DIS + node];
    float4 hv = h[(size_t)node*64 + c4];
    float w0 = di * di;
    float4 v = make_float4(hv.x*w0, hv.y*w0, hv.z*w0, hv.w*w0);
    int n = g_i[OI_CNT + node];
    const int* a = &g_i[OI_ADJ + (size_t)node*MAXDEG];
    for (int e = 0; e < n; e++) {
        int s = a[e];
        float w = g_f[OF_DIS + s] * di;
        float4 hn = h[(size_t)s*64 + c4];
        v.x += hn.x*w; v.y += hn.y*w; v.z += hn.z*w; v.w += hn.w*w;
    }
    float4 b = ((const float4*)bias)[c4];
    float4 o = make_float4(tanhf(v.x + b.x), tanhf(v.y + b.y),
                           tanhf(v.z + b.z), tanhf(v.w + b.w));
    ((float4*)(g_f + outOff))[(size_t)node*64 + c4] = o;
}

// layer-4 projection: h4[n] = dot(x3[n,:256], W4)  (warp per node)
__global__ void k_l4(const float* __restrict__ W4) {
    int warp = (blockIdx.x*blockDim.x + threadIdx.x) >> 5;
    int lane = threadIdx.x & 31;
    if (warp >= Nn) return;
    const float* row = g_f + OF_X3 + (size_t)warp*256;
    float s = 0.f;
    #pragma unroll
    for (int c = lane; c < 256; c += 32) s += row[c] * W4[c];
    #pragma unroll
    for (int o = 16; o; o >>= 1) s += __shfl_xor_sync(0xffffffffu, s, o);
    if (lane == 0) g_f[OF_H4 + warp] = s;
}

// aggregation C=1 + tanh -> x4
__global__ void k_agg1(const float* __restrict__ b4) {
    int i = blockIdx.x*blockDim.x + threadIdx.x;
    if (i >= Nn) return;
    const float* h = g_f + OF_H4;
    float di = g_f[OF_DIS + i];
    float v = h[i] * di * di;
    int n = g_i[OI_CNT + i];
    const int* a = &g_i[OI_ADJ + (size_t)i*MAXDEG];
    for (int e = 0; e < n; e++) { int s = a[e]; v += h[s] * g_f[OF_DIS + s] * di; }
    g_f[OF_X4 + i] = tanhf(v + b4[0]);
}

// per-graph top-K by last channel: bitonic sort of 256 (value desc, idx asc)
__global__ void k_topk() {
    __shared__ float key[256];
    __shared__ int   val[256];
    int g = blockIdx.x, t = threadIdx.x;
    key[t] = (t < NPGc) ? g_f[OF_X4 + (size_t)g*NPGc + t] : -2.0f;  // tanh in (-1,1)
    val[t] = t;
    __syncthreads();
    for (int k = 2; k <= 256; k <<= 1) {
        for (int j = k >> 1; j > 0; j >>= 1) {
            int ixj = t ^ j;
            if (ixj > t) {
                float ka = key[t], kb = key[ixj];
                int   va = val[t], vb = val[ixj];
                bool before = (ka > kb) || (ka == kb && va < vb);
                bool dir = ((t & k) == 0);
                if (before != dir) { key[t]=kb; key[ixj]=ka; val[t]=vb; val[ixj]=va; }
            }
            __syncthreads();
        }
    }
    if (t < KTOP) g_i[OI_IDX + g*KTOP + t] = val[t];
}

// gather selected rows into xs [G*K, 784] (cols 769..783 remain zero)
__global__ void k_gather() {
    int m = blockIdx.x;                 // 0..15839
    int g = m / KTOP;
    int node = g*NPGc + g_i[OI_IDX + m];
    int c = threadIdx.x;
    float* row = g_f + OF_XS + (size_t)m * DdP;
    row[c]       = g_f[OF_X1 + (size_t)node*256 + c];
    row[256 + c] = g_f[OF_X2 + (size_t)node*256 + c];
    row[512 + c] = g_f[OF_X3 + (size_t)node*256 + c];
    if (c == 0) row[768] = g_f[OF_X4 + node];
}

// weight re-layouts
__global__ void k_w5t(const float* __restrict__ w5) {
    int i = blockIdx.x*blockDim.x + threadIdx.x;
    if (i >= 769*128) return;
    int d = i >> 7, oc = i & 127;
    g_f[OF_W5T + i] = w5[oc*Dd + d];    // rows 769..783 of [784,128] stay zero
}
__global__ void k_w6t(const float* __restrict__ w6) {
    int i = blockIdx.x*blockDim.x + threadIdx.x;
    if (i >= 640*256) return;
    int k = i >> 8, o = i & 255;
    int ic = k & 127, j = k >> 7;
    g_f[OF_W6T + i] = w6[o*640 + ic*5 + j];
}
__global__ void k_off6() {
    int m = blockIdx.x*blockDim.x + threadIdx.x;
    if (m >= 5808) return;
    int g = m / 11, t = m - g*11;
    g_i[OI_AOF + m] = g*15*128 + t*128;   // A row start inside y2 buffer
    g_i[OI_COF + m] = g*2816 + t;         // out6 base; +oc2*11
}

// maxpool(2,2) over conv5 output -> y2 [G,15,128]
__global__ void k_pool() {
    int i = blockIdx.x*blockDim.x + threadIdx.x;
    if (i >= Gg*15*128) return;
    int oc = i & 127;
    int r = i >> 7;
    int p = r % 15, g = r / 15;
    float a = g_f[OF_Y5 + (size_t)(g*30 + 2*p)*128 + oc];
    float b = g_f[OF_Y5 + (size_t)(g*30 + 2*p + 1)*128 + oc];
    g_f[OF_Y2 + i] = fmaxf(a, b);
}

// transpose emb (=out6) [48,30976] -> embT [30976,48]
__global__ void k_embT() {
    int k = blockIdx.x*blockDim.x + threadIdx.x;
    if (k >= 30976) return;
    #pragma unroll 4
    for (int b = 0; b < 48; b++)
        g_f[OF_EMT + (size_t)k*48 + b] = g_f[OF_O6 + (size_t)b*30976 + k];
}

// dense1: hpre[b,o] += sum_k emb[b,k]*Wc1[k,o]  (split-K, atomic reduce)
__global__ __launch_bounds__(256)
void k_dense1(const float* __restrict__ Wc1) {
    const int KC = 242;                 // 128 blocks * 242 = 30976
    int o = threadIdx.x;
    int k0 = blockIdx.x * KC;
    float acc[48];
    #pragma unroll
    for (int b = 0; b < 48; b++) acc[b] = 0.f;
    __shared__ __align__(16) float esm[22*48];
    for (int s = 0; s < KC; s += 22) {
        for (int l = threadIdx.x; l < 22*48; l += 256)
            esm[l] = g_f[OF_EMT + (size_t)(k0+s)*48 + l];
        __syncthreads();
        #pragma unroll 2
        for (int kk = 0; kk < 22; kk++) {
            float w = Wc1[(size_t)(k0+s+kk)*256 + o];
            const float4* e4 = (const float4*)&esm[kk*48];
            #pragma unroll
            for (int bb = 0; bb < 12; bb++) {
                float4 e = e4[bb];
                acc[bb*4+0] += e.x*w; acc[bb*4+1] += e.y*w;
                acc[bb*4+2] += e.z*w; acc[bb*4+3] += e.w*w;
            }
        }
        __syncthreads();
    }
    #pragma unroll
    for (int b = 0; b < 48; b++) atomicAdd(&g_f[OF_HP + b*256 + o], acc[b]);
}

// dense2: relu(hpre+bc1) @ Wc2 + bc2 -> logits [48,10]
__global__ void k_dense2(const float* __restrict__ bc1, const float* __restrict__ Wc2,
                         const float* __restrict__ bc2, float* __restrict__ out) {
    __shared__ float hs[48*256];
    int tid = threadIdx.x;
    for (int l = tid; l < 48*256; l += blockDim.x)
        hs[l] = fmaxf(g_f[OF_HP + l] + bc1[l & 255], 0.f);
    __syncthreads();
    if (tid < 480) {
        int b = tid / 10, o = tid - b*10;
        float s = bc2[o];
        for (int j = 0; j < 256; j++) s += hs[b*256 + j] * Wc2[j*10 + o];
        out[tid] = s;
    }
}

// ---------------- launch (kernel launches ONLY — no other CUDA APIs) --------
extern "C" void kernel_launch(void* const* d_in, const int* in_sizes, int n_in,
                              void* d_out, int out_size) {
    const float* x    = (const float*)d_in[0];
    const int*   src  = (const int*)  d_in[1];
    const int*   dstp = (const int*)  d_in[2];
    const float* W1   = (const float*)d_in[3];
    const float* b1   = (const float*)d_in[4];
    const float* W2   = (const float*)d_in[5];
    const float* b2   = (const float*)d_in[6];
    const float* W3   = (const float*)d_in[7];
    const float* b3   = (const float*)d_in[8];
    const float* W4   = (const float*)d_in[9];
    const float* b4   = (const float*)d_in[10];
    const float* w5   = (const float*)d_in[11];
    const float* bc5  = (const float*)d_in[12];
    const float* w6   = (const float*)d_in[13];
    const float* bc6  = (const float*)d_in[14];
    const float* Wc1  = (const float*)d_in[15];
    const float* bc1  = (const float*)d_in[16];
    const float* Wc2  = (const float*)d_in[17];
    const float* bc2  = (const float*)d_in[18];
    float* out = (float*)d_out;

    // graph structure
    k_zero_cnt<<<(Nn+255)/256, 256>>>();
    k_build<<<(Ee+255)/256, 256>>>(src, dstp);
    k_dis<<<(Nn+255)/256, 256>>>();

    // GCN layers: XW (into H) then normalize+aggregate+tanh
    // layer 1 (K=64, T=4): per-tile blocks (mtiles stream measured harmful at T=4)
    sgemm2<<<dim3(2,792), 256>>>(x, 0, 64, 0, 1,  W1, 0, OF_H, 0, 1, Nn, 256, 64,  nullptr, 0, 1);
    k_agg<<<Nn/4, 256>>>(OF_X1, b1);
    // layers 2/3 (K=256, T=16): one-wave multi-tile streams (measured best)
    sgemm2<<<dim3(2,132), 256>>>(nullptr, OF_X1, 256, 0, 1, W2, 0, OF_H, 0, 1, Nn, 256, 256, nullptr, 0, 6);
    k_agg<<<Nn/4, 256>>>(OF_X2, b2);
    sgemm2<<<dim3(2,132), 256>>>(nullptr, OF_X2, 256, 0, 1, W3, 0, OF_H, 0, 1, Nn, 256, 256, nullptr, 0, 6);
    k_agg<<<Nn/4, 256>>>(OF_X3, b3);
    k_l4<<<(Nn*32+255)/256, 256>>>(W4);
    k_agg1<<<(Nn+255)/256, 256>>>(b4);

    // sort-pool + gather
    k_topk<<<Gg, 256>>>();
    k_gather<<<Gg*KTOP, 256>>>();

    // weight re-layouts + offset tables (needed only before conv5/conv6)
    k_w5t<<<(769*128+255)/256, 256>>>(w5);
    k_w6t<<<(640*256+255)/256, 256>>>(w6);
    k_off6<<<(5808+255)/256, 256>>>();

    // conv5 as GEMM [15840,784(padded)]x[784,128] + bias + relu — fast vecA path
    sgemm2<<<dim3(1,124), 256>>>(nullptr, OF_XS, DdP, 0, 1, nullptr, OF_W5T, OF_Y5, 0, 1,
                                 Gg*KTOP, 128, DdP, bc5, 1, 1);
    k_pool<<<(Gg*15*128+255)/256, 256>>>();

    // conv6 as GEMM with row-offset indirection [5808,640]x[640,256], permuted store
    sgemm2<<<dim3(2,46), 256>>>(nullptr, OF_Y2, 0, 1, 1, nullptr, OF_W6T, OF_O6, 1, 11,
                                5808, 256, 640, bc6, 1, 1);

    // dense head
    k_embT<<<(30976+255)/256, 256>>>();
    k_zero_hp<<<(48*256+255)/256, 256>>>();
    k_dense1<<<128, 256>>>(Wc1);
    k_dense2<<<1, 512>>>(bc1, Wc2, bc2, out);
}